// round 6
// baseline (speedup 1.0000x reference)
#include <cuda_runtime.h>
#include <cuda_bf16.h>

// Problem constants (fixed by the dataset builder)
#define BB    64          // batches
#define SS    4096        // spikes per batch
#define LL    25          // Lmax
#define NBINS 3600        // OH*OW
#define CAPC  128         // cap
#define NC    128         // chunks per batch
#define CHUNK (SS / NC)   // 32 spikes per chunk
#define NSC   32          // superchunks of 128 spikes (4 chunks) for packed count
#define OFFCLAMP 160u     // offsets >= 128 are dead; clamp keeps u8 exact where live

#define FILL_BLOCKS 7200
#define COUNT_BLOCKS (BB * NSC)   // 2048

// Scratch (static device globals — allocation-free per harness rules)
// g_counts[b][sc][bin]: 4 chunks' counts in the 4 byte fields (each <= 32).
__device__ unsigned int  g_counts[BB * NSC * NBINS];           // 29.5 MB (L2-resident)
__device__ unsigned char g_off[(size_t)BB * NC * NBINS];       // 29.5 MB, clamped u8

// ---------------------------------------------------------------------------
// Kernel 1: FUSED fill + count. Blocks [0, FILL_BLOCKS) stream -1.0f into the
// output (118 MB, DRAM-bound). Blocks [FILL_BLOCKS, +COUNT_BLOCKS) build the
// packed per-chunk histograms (L2 gathers + smem atomics). Independent work,
// concurrent in one grid -> DRAM and L2/LSU phases overlap.
// Count block: superchunk of 128 spikes = 4 chunks of 32. 8 warps; warps
// 2q,2q+1 count chunk q into byte field q (add = 1<<(8q)); fields <= 32.
// ---------------------------------------------------------------------------
__global__ void fill_count_kernel(float4* __restrict__ out,
                                  const int* __restrict__ spikes,
                                  const int* __restrict__ indices) {
    if (blockIdx.x < FILL_BLOCKS) {
        int i = blockIdx.x * 256 + threadIdx.x;
        float4 v = make_float4(-1.0f, -1.0f, -1.0f, -1.0f);
        int base = i * 4;
        out[base + 0] = v;
        out[base + 1] = v;
        out[base + 2] = v;
        out[base + 3] = v;
        return;
    }

    __shared__ unsigned int hist[NBINS];
    int tid = threadIdx.x;
    for (int i = tid; i < NBINS; i += 256) hist[i] = 0u;
    __syncthreads();

    int blk = blockIdx.x - FILL_BLOCKS;
    int b  = blk >> 5;   // NSC == 32
    int sc = blk & 31;
    int warp = tid >> 5, lane = tid & 31;
    int q = warp >> 1;                 // chunk within superchunk (0..3)
    int h = warp & 1;                  // half of the chunk
    const int* sp = spikes + b * SS + sc * 128 + q * 32 + h * 16;
    unsigned int add = 1u << (8 * q);

    for (int k = 0; k < 16; k++) {
        int id = __ldg(&sp[k]);                      // uniform broadcast load
        int j = -1;
        if (lane < LL) j = __ldg(&indices[id * LL + lane]);
        if (j >= 0) {
            unsigned int bin = (unsigned int)j % (unsigned int)NBINS;
            atomicAdd(&hist[bin], add);
        }
    }
    __syncthreads();

    unsigned int* dst = g_counts + (size_t)blk * NBINS;
    for (int i = tid; i < NBINS; i += 256) dst[i] = hist[i];
}

// ---------------------------------------------------------------------------
// Kernel 2: exclusive scan over 128 chunks per (b,bin). Reads packed byte
// counts (L2-resident), writes u8 offsets clamped to OFFCLAMP.
// Thread per (b,bin): coalesced u32 reads, coalesced byte writes.
// ---------------------------------------------------------------------------
__global__ void scan_kernel() {
    int idx = blockIdx.x * 256 + threadIdx.x;
    if (idx >= BB * NBINS) return;
    int b = idx / NBINS;
    int bin = idx - b * NBINS;
    unsigned int sum = 0;
#pragma unroll
    for (int sc = 0; sc < NSC; sc++) {
        unsigned int v = g_counts[((size_t)(b * NSC + sc)) * NBINS + bin];
#pragma unroll
        for (int sub = 0; sub < 4; sub++) {
            int c = sc * 4 + sub;
            g_off[((size_t)(b * NC + c)) * NBINS + bin] =
                (unsigned char)min(sum, OFFCLAMP);
            sum += (v >> (8 * sub)) & 0xFFu;
        }
    }
}

// ---------------------------------------------------------------------------
// Kernel 3: ordered scatter. One WARP per (b,chunk) of 32 spikes; 8 warps per
// block (28.8 KB u8 counters -> 7 blocks/SM = 56 warps/SM, ~87% occ).
// Depth-4 software pipeline: next group's 4 indices rows gathered while the
// current 4 process serially. Spike ids batch-loaded into one reg/lane.
// Counter max = 160(clamp) + 32(chunk) = 192 < 256 -> u8 exact where live.
// Ordering: within one spike the 25 bins are distinct so lanes never collide;
// __syncwarp between spikes orders the byte RMWs across spikes.
// ---------------------------------------------------------------------------
__global__ void scatter_kernel(const int* __restrict__ spikes,
                               const int* __restrict__ indices,
                               float* __restrict__ out) {
    __shared__ __align__(16) unsigned char cnt[8 * NBINS];   // 28.8 KB
    const unsigned int FULL = 0xffffffffu;
    int warp = threadIdx.x >> 5, lane = threadIdx.x & 31;
    int chunk = blockIdx.x * 8 + warp;
    int b = chunk >> 7;        // NC == 128
    int c = chunk & 127;

    // uint4 preload of u8 counters (3600 B = 225 uint4 per warp).
    unsigned char* my = cnt + warp * NBINS;
    {
        const uint4* offv = (const uint4*)(g_off + (size_t)chunk * NBINS);
        uint4* myv = (uint4*)my;
        for (int i = lane; i < NBINS / 16; i += 32) myv[i] = __ldg(&offv[i]);
    }

    const int* sp = spikes + b * SS + c * CHUNK;
    int idall = __ldg(&sp[lane]);       // spikes 0..31 of this chunk
    float* outb = out + (size_t)b * CAPC * NBINS;
    bool act = lane < LL;
    __syncwarp();

    #define GATHER(dst, s) do {                                              \
        int _id = __shfl_sync(FULL, idall, (s));                             \
        (dst) = act ? __ldg(&indices[_id * LL + lane]) : -1;                 \
    } while (0)

    #define PROCESS(jv) do {                                                 \
        if ((jv) >= 0) {                                                     \
            unsigned int ju  = (unsigned int)(jv);                           \
            unsigned int ckk = ju / (unsigned int)NBINS;                     \
            unsigned int bin = ju - ckk * (unsigned int)NBINS;               \
            unsigned int r = my[bin];                                        \
            my[bin] = (unsigned char)(r + 1u);                               \
            if (r < CAPC) outb[(size_t)r * NBINS + bin] = (float)ckk;        \
        }                                                                    \
        __syncwarp();                                                        \
    } while (0)

    int j0, j1, j2, j3;
    GATHER(j0, 0); GATHER(j1, 1); GATHER(j2, 2); GATHER(j3, 3);

    #pragma unroll
    for (int g = 0; g < CHUNK / 4 - 1; g++) {
        int s = g * 4;
        int n0, n1, n2, n3;
        GATHER(n0, s + 4); GATHER(n1, s + 5);
        GATHER(n2, s + 6); GATHER(n3, s + 7);
        PROCESS(j0); PROCESS(j1); PROCESS(j2); PROCESS(j3);
        j0 = n0; j1 = n1; j2 = n2; j3 = n3;
    }
    PROCESS(j0); PROCESS(j1); PROCESS(j2); PROCESS(j3);

    #undef GATHER
    #undef PROCESS
}

// ---------------------------------------------------------------------------
extern "C" void kernel_launch(void* const* d_in, const int* in_sizes, int n_in,
                              void* d_out, int out_size) {
    const int* spikes  = (const int*)d_in[0];   // (64, 4096, 1, 1) int32
    const int* indices = (const int*)d_in[1];   // (131072, 25) int32
    float* out = (float*)d_out;                 // (64, 128, 60, 60) float32

    fill_count_kernel<<<FILL_BLOCKS + COUNT_BLOCKS, 256>>>((float4*)out,
                                                           spikes, indices);
    scan_kernel<<<(BB * NBINS + 255) / 256, 256>>>();
    scatter_kernel<<<BB * NC / 8, 256>>>(spikes, indices, out);
}

// round 7
// speedup vs baseline: 1.1840x; 1.1840x over previous
#include <cuda_runtime.h>
#include <cuda_bf16.h>

// Problem constants (fixed by the dataset builder)
#define BB    64          // batches
#define SS    4096        // spikes per batch
#define LL    25          // Lmax
#define NBINS 3600        // OH*OW
#define CAPC  128         // cap
#define NC    64          // chunks per batch
#define CHUNK (SS / NC)   // 64 spikes per chunk
#define NSC   16          // superchunks of 256 spikes (4 chunks) for packed count
#define OFFCLAMP 160u     // offsets >= 128 are dead; clamp keeps u8 exact where live

// Scratch (static device globals — allocation-free per harness rules)
// g_counts[b][sc][bin]: 4 chunks' counts in the 4 byte fields (each <= 64).
__device__ unsigned int  g_counts[BB * NSC * NBINS];          // 14.7 MB
__device__ unsigned char g_off[(size_t)BB * NC * NBINS];      // 14.7 MB, clamped u8

// ---------------------------------------------------------------------------
// Kernel 1: fill output with -1.0f (118 MB, DRAM roofline-bound).
// ---------------------------------------------------------------------------
__global__ void fill_kernel(float4* __restrict__ out) {
    int i = blockIdx.x * blockDim.x + threadIdx.x;
    float4 v = make_float4(-1.0f, -1.0f, -1.0f, -1.0f);
    int base = i * 4;
    out[base + 0] = v;
    out[base + 1] = v;
    out[base + 2] = v;
    out[base + 3] = v;
}

// ---------------------------------------------------------------------------
// Kernel 2: packed per-chunk histogram. One block (256 thr = 8 warps) per
// superchunk of 256 spikes = 4 chunks of 64. Warps 2k,2k+1 count chunk k
// into byte field k (add = 1<<(8k)). Fields never exceed 64 -> no carry.
// ---------------------------------------------------------------------------
__global__ void count_kernel(const int* __restrict__ spikes,
                             const int* __restrict__ indices) {
    __shared__ unsigned int hist[NBINS];
    int tid = threadIdx.x;
    for (int i = tid; i < NBINS; i += 256) hist[i] = 0u;
    __syncthreads();

    int b  = blockIdx.x >> 4;   // NSC == 16
    int sc = blockIdx.x & 15;
    int warp = tid >> 5, lane = tid & 31;
    const int* sp = spikes + b * SS + sc * 256 + warp * 32;
    unsigned int add = 1u << (8 * (warp >> 1));

    for (int k = 0; k < 32; k++) {
        int id = __ldg(&sp[k]);                      // uniform broadcast load
        int j = -1;
        if (lane < LL) j = __ldg(&indices[id * LL + lane]);
        if (j >= 0) {
            unsigned int bin = (unsigned int)j % (unsigned int)NBINS;
            atomicAdd(&hist[bin], add);
        }
    }
    __syncthreads();

    unsigned int* dst = g_counts + (size_t)blockIdx.x * NBINS;
    for (int i = tid; i < NBINS; i += 256) dst[i] = hist[i];
}

// ---------------------------------------------------------------------------
// Kernel 3: exclusive scan over 64 chunks per (b,bin). Reads packed byte
// counts, writes u8 offsets clamped to OFFCLAMP (dead >= 128 anyway).
// ---------------------------------------------------------------------------
__global__ void scan_kernel() {
    int idx = blockIdx.x * 256 + threadIdx.x;
    if (idx >= BB * NBINS) return;
    int b = idx / NBINS;
    int bin = idx - b * NBINS;
    unsigned int sum = 0;
#pragma unroll
    for (int sc = 0; sc < NSC; sc++) {
        unsigned int v = g_counts[((size_t)(b * NSC + sc)) * NBINS + bin];
#pragma unroll
        for (int sub = 0; sub < 4; sub++) {
            int c = sc * 4 + sub;
            g_off[((size_t)(b * NC + c)) * NBINS + bin] =
                (unsigned char)min(sum, OFFCLAMP);
            sum += (v >> (8 * sub)) & 0xFFu;
        }
    }
}

// ---------------------------------------------------------------------------
// Kernel 4: ordered scatter. One WARP per (b,chunk) of 64 spikes; 4 warps per
// block, 14.4 KB u8 counters. DEPTH-8 software pipeline: two 4-spike groups'
// gathers in flight while the current group processes -> each gather gets
// ~2 groups (~480+ cyc) of cover, exceeding NAT-clock L2 latency.
// Counter max = 160(clamp) + 64(chunk) = 224 < 256 -> u8 exact where live.
// Ordering: within one spike the 25 bins are distinct so lanes never collide;
// __syncwarp between spikes orders the byte RMWs across spikes.
// ---------------------------------------------------------------------------
__global__ void scatter_kernel(const int* __restrict__ spikes,
                               const int* __restrict__ indices,
                               float* __restrict__ out) {
    __shared__ __align__(16) unsigned char cnt[4 * NBINS];   // 14.4 KB
    const unsigned int FULL = 0xffffffffu;
    int warp = threadIdx.x >> 5, lane = threadIdx.x & 31;
    int chunk = blockIdx.x * 4 + warp;
    int b = chunk >> 6;        // NC == 64
    int c = chunk & 63;

    // uint4 preload of u8 counters (3600 B = 225 uint4 per warp).
    unsigned char* my = cnt + warp * NBINS;
    {
        const uint4* offv = (const uint4*)(g_off + (size_t)chunk * NBINS);
        uint4* myv = (uint4*)my;
        for (int i = lane; i < NBINS / 16; i += 32) myv[i] = __ldg(&offv[i]);
    }

    const int* sp = spikes + b * SS + c * CHUNK;
    int idlo = __ldg(&sp[lane]);        // spikes 0..31
    int idhi = __ldg(&sp[32 + lane]);   // spikes 32..63
    float* outb = out + (size_t)b * CAPC * NBINS;
    bool act = lane < LL;
    __syncwarp();

    #define GATHER(dst, s) do {                                              \
        int _id = ((s) < 32) ? __shfl_sync(FULL, idlo, (s))                  \
                             : __shfl_sync(FULL, idhi, (s) - 32);            \
        (dst) = act ? __ldg(&indices[_id * LL + lane]) : -1;                 \
    } while (0)

    #define PROCESS(jv) do {                                                 \
        if ((jv) >= 0) {                                                     \
            unsigned int ju  = (unsigned int)(jv);                           \
            unsigned int ckk = ju / (unsigned int)NBINS;                     \
            unsigned int bin = ju - ckk * (unsigned int)NBINS;               \
            unsigned int r = my[bin];                                        \
            my[bin] = (unsigned char)(r + 1u);                               \
            if (r < CAPC) outb[(size_t)r * NBINS + bin] = (float)ckk;        \
        }                                                                    \
        __syncwarp();                                                        \
    } while (0)

    // Depth-8 pipeline: groups A (current), B (next), C (next-next in flight).
    int a0, a1, a2, a3, b0, b1, b2, b3;
    GATHER(a0, 0); GATHER(a1, 1); GATHER(a2, 2); GATHER(a3, 3);
    GATHER(b0, 4); GATHER(b1, 5); GATHER(b2, 6); GATHER(b3, 7);

    #pragma unroll 4
    for (int g = 0; g < CHUNK / 4 - 2; g++) {
        int s = g * 4;
        int c0, c1, c2, c3;
        GATHER(c0, s + 8); GATHER(c1, s + 9);
        GATHER(c2, s + 10); GATHER(c3, s + 11);
        PROCESS(a0); PROCESS(a1); PROCESS(a2); PROCESS(a3);
        a0 = b0; a1 = b1; a2 = b2; a3 = b3;
        b0 = c0; b1 = c1; b2 = c2; b3 = c3;
    }
    PROCESS(a0); PROCESS(a1); PROCESS(a2); PROCESS(a3);
    PROCESS(b0); PROCESS(b1); PROCESS(b2); PROCESS(b3);

    #undef GATHER
    #undef PROCESS
}

// ---------------------------------------------------------------------------
extern "C" void kernel_launch(void* const* d_in, const int* in_sizes, int n_in,
                              void* d_out, int out_size) {
    const int* spikes  = (const int*)d_in[0];   // (64, 4096, 1, 1) int32
    const int* indices = (const int*)d_in[1];   // (131072, 25) int32
    float* out = (float*)d_out;                 // (64, 128, 60, 60) float32

    fill_kernel<<<7200, 256>>>((float4*)out);
    count_kernel<<<BB * NSC, 256>>>(spikes, indices);
    scan_kernel<<<(BB * NBINS + 255) / 256, 256>>>();
    scatter_kernel<<<BB * NC / 4, 128>>>(spikes, indices, out);
}